// round 2
// baseline (speedup 1.0000x reference)
#include <cuda_runtime.h>
#include <math.h>

// Problem constants
#define Bc   32
#define Nn   4096
#define FDc  256
#define Dc   256
#define Hc   4
#define NFc  8
#define DHc  64
#define SCALEF 0.125f     // DH^-0.5
#define EPSF   1e-8f
#define LNEPS  1e-5f

// -------- scratch (device globals: allocation-free) --------
__device__ float g_stats[2 * 131072];          // per-row mean,rstd of inputs
__device__ float g_K[33554432];                // [B,N,256]
__device__ float g_V[33554432];                // [B,N,256]
__device__ float g_attn[32 * 32 * 4096];       // [b][ih][j] raw softmax
__device__ float g_rowsum[1024];               // [b][ih]
__device__ float g_fill[65536];                // fillers [b,slot,256]
__device__ float g_f[65536];                   // LN(fillers)
__device__ float g_q[65536];                   // q
__device__ float g_upd[65536];                 // updates
__device__ float g_gates[2 * 256 * 768];       // [gi|gh][row][768]

// ---------------- row stats of inputs (mean, rstd over FD=256) ----------------
__global__ void k_rowstats(const float* __restrict__ x) {
    int warp = (blockIdx.x * blockDim.x + threadIdx.x) >> 5;   // row id
    int lane = threadIdx.x & 31;
    const float* r = x + (size_t)warp * 256;
    float v[8];
    float s = 0.f;
#pragma unroll
    for (int u = 0; u < 8; u++) { v[u] = r[lane + 32 * u]; s += v[u]; }
#pragma unroll
    for (int o = 16; o > 0; o >>= 1) s += __shfl_xor_sync(0xffffffffu, s, o);
    float m = s * (1.f / 256.f);
    float ss = 0.f;
#pragma unroll
    for (int u = 0; u < 8; u++) { float d = v[u] - m; ss += d * d; }
#pragma unroll
    for (int o = 16; o > 0; o >>= 1) ss += __shfl_xor_sync(0xffffffffu, ss, o);
    if (lane == 0) {
        g_stats[2 * warp + 0] = m;
        g_stats[2 * warp + 1] = rsqrtf(ss * (1.f / 256.f) + LNEPS);
    }
}

// ---------------- big GEMM: K = LN(x) @ Wk^T, V = LN(x) @ Wv^T ----------------
// 128x128 tile, TK=16, 256 threads, 8x8 microtile. LN fused into A-tile load.
__global__ void __launch_bounds__(256, 2)
k_kv_gemm(const float* __restrict__ x,
          const float* __restrict__ Wk, const float* __restrict__ Wv,
          const float* __restrict__ lg, const float* __restrict__ lb) {
    __shared__ float As[128][17];
    __shared__ float Bs[128][17];
    __shared__ float gs[256], bsm[256];

    int t = threadIdx.x;
    gs[t]  = lg[t];
    bsm[t] = lb[t];

    int row0 = blockIdx.x * 128;
    int col0 = blockIdx.y * 128;
    const float* W = blockIdx.z ? Wv : Wk;
    float* out     = blockIdx.z ? g_V : g_K;

    int tx = t & 15, ty = t >> 4;

    float acc[8][8];
#pragma unroll
    for (int i = 0; i < 8; i++)
#pragma unroll
        for (int j = 0; j < 8; j++) acc[i][j] = 0.f;

    for (int k0 = 0; k0 < 256; k0 += 16) {
        __syncthreads();
#pragma unroll
        for (int s = 0; s < 2; s++) {
            int f = t + 256 * s;
            int row = f >> 2, kp = f & 3;
            int rg = row0 + row;
            float4 a4 = *(const float4*)(x + (size_t)rg * 256 + k0 + kp * 4);
            float m   = g_stats[2 * rg + 0];
            float rsd = g_stats[2 * rg + 1];
            int kc = k0 + kp * 4;
            As[row][kp * 4 + 0] = (a4.x - m) * rsd * gs[kc + 0] + bsm[kc + 0];
            As[row][kp * 4 + 1] = (a4.y - m) * rsd * gs[kc + 1] + bsm[kc + 1];
            As[row][kp * 4 + 2] = (a4.z - m) * rsd * gs[kc + 2] + bsm[kc + 2];
            As[row][kp * 4 + 3] = (a4.w - m) * rsd * gs[kc + 3] + bsm[kc + 3];
            float4 b4 = *(const float4*)(W + (size_t)(col0 + row) * 256 + k0 + kp * 4);
            Bs[row][kp * 4 + 0] = b4.x;
            Bs[row][kp * 4 + 1] = b4.y;
            Bs[row][kp * 4 + 2] = b4.z;
            Bs[row][kp * 4 + 3] = b4.w;
        }
        __syncthreads();
#pragma unroll
        for (int kk = 0; kk < 16; kk++) {
            float a[8], bb[8];
#pragma unroll
            for (int i = 0; i < 8; i++) a[i]  = As[ty + 16 * i][kk];
#pragma unroll
            for (int j = 0; j < 8; j++) bb[j] = Bs[tx + 16 * j][kk];
#pragma unroll
            for (int i = 0; i < 8; i++)
#pragma unroll
                for (int j = 0; j < 8; j++) acc[i][j] += a[i] * bb[j];
        }
    }
#pragma unroll
    for (int i = 0; i < 8; i++)
#pragma unroll
        for (int j = 0; j < 8; j++)
            out[(size_t)(row0 + ty + 16 * i) * 256 + col0 + tx + 16 * j] = acc[i][j];
}

// ---------------- small GEMM: C[256 x Ncols] = A[256,256] @ W[Ncols,256]^T + bias
// mode 0: A=g_f   -> C=g_q            (ldc 256, no bias)
// mode 1: A=g_upd -> C=g_gates        (ldc 768, bias b_ih)
// mode 2: A=g_fill-> C=g_gates+196608 (ldc 768, bias b_hh)
__global__ void __launch_bounds__(256)
k_gemm64(int mode, const float* __restrict__ W, const float* __restrict__ bias) {
    const float* A;
    float* C;
    int ldc;
    if (mode == 0)      { A = g_f;    C = g_q;              ldc = 256; }
    else if (mode == 1) { A = g_upd;  C = g_gates;          ldc = 768; }
    else                { A = g_fill; C = g_gates + 196608; ldc = 768; }

    __shared__ float As[64][17];
    __shared__ float Bs[64][17];
    int t = threadIdx.x;
    int row0 = blockIdx.x * 64, col0 = blockIdx.y * 64;
    int tx = t & 15, ty = t >> 4;

    float acc[4][4];
#pragma unroll
    for (int i = 0; i < 4; i++)
#pragma unroll
        for (int j = 0; j < 4; j++) acc[i][j] = 0.f;

    for (int k0 = 0; k0 < 256; k0 += 16) {
        __syncthreads();
        {
            int row = t >> 2, kp = t & 3;
            float4 a4 = *(const float4*)(A + (size_t)(row0 + row) * 256 + k0 + kp * 4);
            As[row][kp * 4 + 0] = a4.x;
            As[row][kp * 4 + 1] = a4.y;
            As[row][kp * 4 + 2] = a4.z;
            As[row][kp * 4 + 3] = a4.w;
            float4 b4 = *(const float4*)(W + (size_t)(col0 + row) * 256 + k0 + kp * 4);
            Bs[row][kp * 4 + 0] = b4.x;
            Bs[row][kp * 4 + 1] = b4.y;
            Bs[row][kp * 4 + 2] = b4.z;
            Bs[row][kp * 4 + 3] = b4.w;
        }
        __syncthreads();
#pragma unroll
        for (int kk = 0; kk < 16; kk++) {
            float a[4], bb[4];
#pragma unroll
            for (int i = 0; i < 4; i++) a[i]  = As[ty + 16 * i][kk];
#pragma unroll
            for (int j = 0; j < 4; j++) bb[j] = Bs[tx + 16 * j][kk];
#pragma unroll
            for (int i = 0; i < 4; i++)
#pragma unroll
                for (int j = 0; j < 4; j++) acc[i][j] += a[i] * bb[j];
        }
    }
#pragma unroll
    for (int i = 0; i < 4; i++)
#pragma unroll
        for (int j = 0; j < 4; j++) {
            float c = acc[i][j];
            if (bias) c += bias[col0 + tx + 16 * j];
            C[(size_t)(row0 + ty + 16 * i) * ldc + col0 + tx + 16 * j] = c;
        }
}

// ---------------- LN(fillers) + zero rowsum + zero g_upd ----------------
__global__ void k_lnfill(const float* __restrict__ g, const float* __restrict__ b) {
    int t = threadIdx.x;
    int gt = blockIdx.x * 256 + t;         // 8192 threads total
#pragma unroll
    for (int u = 0; u < 8; u++) g_upd[gt + 8192 * u] = 0.f;
    if (gt < 1024) g_rowsum[gt] = 0.f;

    int row  = blockIdx.x * 8 + (t >> 5);  // 256 rows total
    int lane = t & 31;
    const float* r = g_fill + row * 256;
    float v[8];
    float s = 0.f;
#pragma unroll
    for (int u = 0; u < 8; u++) { v[u] = r[lane + 32 * u]; s += v[u]; }
#pragma unroll
    for (int o = 16; o > 0; o >>= 1) s += __shfl_xor_sync(0xffffffffu, s, o);
    float m = s * (1.f / 256.f);
    float ss = 0.f;
#pragma unroll
    for (int u = 0; u < 8; u++) { float d = v[u] - m; ss += d * d; }
#pragma unroll
    for (int o = 16; o > 0; o >>= 1) ss += __shfl_xor_sync(0xffffffffu, ss, o);
    float rstd = rsqrtf(ss * (1.f / 256.f) + LNEPS);
#pragma unroll
    for (int u = 0; u < 8; u++) {
        int c = lane + 32 * u;
        g_f[row * 256 + c] = (v[u] - m) * rstd * g[c] + b[c];
    }
}

// ---------------- dots + inverted softmax (over 32 (slot,head) per (b,j)) ----------------
// grid (32 b, 16 chunks of 256 j), 256 threads (8 warps x 32 contiguous j each).
// lane = ih index (i=lane>>2, h=lane&3). q held in registers (pre-scaled).
__global__ void __launch_bounds__(256)
k_dots(int last, float* __restrict__ attn_out) {
    int b = blockIdx.x;
    int w = threadIdx.x >> 5, lane = threadIdx.x & 31;
    int j0 = blockIdx.y * 256 + w * 32;

    __shared__ float buf[8][32][33];

    int i = lane >> 2, h = lane & 3;
    const float4* q4 = (const float4*)(g_q + b * 2048 + i * 256 + h * 64);
    float4 qr[16];
#pragma unroll
    for (int p = 0; p < 16; p++) {
        float4 q = q4[p];
        q.x *= SCALEF; q.y *= SCALEF; q.z *= SCALEF; q.w *= SCALEF;
        qr[p] = q;
    }

    float rs = 0.f;
    for (int jj = 0; jj < 32; jj++) {
        int j = j0 + jj;
        const float4* k4 = (const float4*)(g_K + (size_t)(b * 4096 + j) * 256 + h * 64);
        float dot = 0.f;
#pragma unroll
        for (int p = 0; p < 16; p++) {
            float4 kv = k4[p];
            dot += qr[p].x * kv.x + qr[p].y * kv.y + qr[p].z * kv.z + qr[p].w * kv.w;
        }
        float mx = dot;
#pragma unroll
        for (int o = 16; o > 0; o >>= 1) mx = fmaxf(mx, __shfl_xor_sync(0xffffffffu, mx, o));
        float e = expf(dot - mx);
        float sm = e;
#pragma unroll
        for (int o = 16; o > 0; o >>= 1) sm += __shfl_xor_sync(0xffffffffu, sm, o);
        float at = e / sm;
        buf[w][lane][jj] = at;
        rs += at;
    }
    atomicAdd(&g_rowsum[b * 32 + lane], rs);
    __syncwarp();

    // coalesced transposed writeback: g_attn[b][ih][j]
#pragma unroll 4
    for (int r = 0; r < 32; r++)
        g_attn[((size_t)b * 32 + r) * 4096 + j0 + lane] = buf[w][r][lane];

    if (last) {
#pragma unroll
        for (int ii = 0; ii < 8; ii++) {
            float v = 0.25f * (buf[w][4 * ii + 0][lane] + buf[w][4 * ii + 1][lane] +
                               buf[w][4 * ii + 2][lane] + buf[w][4 * ii + 3][lane]);
            attn_out[((size_t)b * 8 + ii) * 4096 + j0 + lane] = v;
        }
    }
}

// ---------------- updates = einsum('bjhd,bihj->bihd', V, a) ----------------
// grid (32 b, 4 h, 8 j-chunks of 512), 256 threads: d = t&63, handles 2 slots.
__global__ void __launch_bounds__(256)
k_updates() {
    int b = blockIdx.x, h = blockIdx.y, jc = blockIdx.z;
    int t = threadIdx.x;
    int d = t & 63, ig = t >> 6;
    int i0 = 2 * ig, i1 = i0 + 1;

    __shared__ float a_s[8][64];
    __shared__ float inv_s[8];
    if (t < 8) inv_s[t] = 1.f / (g_rowsum[b * 32 + t * 4 + h] + 4096.f * EPSF);

    float acc0 = 0.f, acc1 = 0.f;
    int jbase = jc * 512;
    for (int jt = 0; jt < 512; jt += 64) {
        __syncthreads();
#pragma unroll
        for (int s = 0; s < 2; s++) {
            int e = t + 256 * s;
            int ri = e >> 6, jj = e & 63;
            a_s[ri][jj] = (g_attn[((size_t)b * 32 + ri * 4 + h) * 4096 + jbase + jt + jj] + EPSF) * inv_s[ri];
        }
        __syncthreads();
        const float* vp = g_V + (size_t)(b * 4096 + jbase + jt) * 256 + h * 64 + d;
#pragma unroll 4
        for (int jj = 0; jj < 64; jj++) {
            float vv = vp[jj * 256];
            acc0 += vv * a_s[i0][jj];
            acc1 += vv * a_s[i1][jj];
        }
    }
    atomicAdd(&g_upd[b * 2048 + i0 * 256 + h * 64 + d], acc0);
    atomicAdd(&g_upd[b * 2048 + i1 * 256 + h * 64 + d], acc1);
}

// ---------------- GRU elementwise ----------------
__global__ void k_gru() {
    int idx = blockIdx.x * blockDim.x + threadIdx.x;   // 65536
    int r = idx >> 8, c = idx & 255;
    const float* gi = g_gates + (size_t)r * 768;
    const float* gh = g_gates + 196608 + (size_t)r * 768;
    float ir = gi[c], iz = gi[c + 256], in = gi[c + 512];
    float hr = gh[c], hz = gh[c + 256], hn = gh[c + 512];
    float rr = 1.f / (1.f + expf(-(ir + hr)));
    float zz = 1.f / (1.f + expf(-(iz + hz)));
    float nn = tanhf(in + rr * hn);
    float hp = g_fill[idx];
    g_fill[idx] = (1.f - zz) * nn + zz * hp;
}

// ---------------- copies ----------------
__global__ void k_copyin(const float* __restrict__ src) {
    int idx = blockIdx.x * blockDim.x + threadIdx.x;
    g_fill[idx] = src[idx];
}
__global__ void k_copyout(float* __restrict__ dst) {
    int idx = blockIdx.x * blockDim.x + threadIdx.x;
    dst[idx] = g_fill[idx];
}

// ---------------- launcher ----------------
extern "C" void kernel_launch(void* const* d_in, const int* in_sizes, int n_in,
                              void* d_out, int out_size) {
    const float* inputs = (const float*)d_in[0];
    const float* cond   = (const float*)d_in[1];
    const float* Wq     = (const float*)d_in[2];
    const float* Wk     = (const float*)d_in[3];
    const float* Wv     = (const float*)d_in[4];
    const float* W_ih   = (const float*)d_in[5];
    const float* W_hh   = (const float*)d_in[6];
    const float* b_ih   = (const float*)d_in[7];
    const float* b_hh   = (const float*)d_in[8];
    const float* lig    = (const float*)d_in[9];
    const float* lib    = (const float*)d_in[10];
    const float* lfg    = (const float*)d_in[11];
    const float* lfb    = (const float*)d_in[12];
    float* out = (float*)d_out;

    k_rowstats<<<16384, 256>>>(inputs);
    k_kv_gemm<<<dim3(1024, 2, 2), 256>>>(inputs, Wk, Wv, lig, lib);
    k_copyin<<<64, 1024>>>(cond);

    for (int it = 0; it < 3; it++) {
        k_lnfill<<<32, 256>>>(lfg, lfb);
        k_gemm64<<<dim3(4, 4), 256>>>(0, Wq, (const float*)0);
        k_dots<<<dim3(32, 16), 256>>>(it == 2 ? 1 : 0, out + 65536);
        k_updates<<<dim3(32, 4, 8), 256>>>();
        k_gemm64<<<dim3(4, 12), 256>>>(1, W_ih, b_ih);
        k_gemm64<<<dim3(4, 12), 256>>>(2, W_hh, b_hh);
        k_gru<<<256, 256>>>();
    }
    k_copyout<<<64, 1024>>>(out);
}

// round 4
// speedup vs baseline: 1.2311x; 1.2311x over previous
#include <cuda_runtime.h>
#include <cuda_bf16.h>
#include <cstdint>
#include <math.h>

// Problem constants
#define Bc   32
#define Nn   4096
#define FDc  256
#define Dc   256
#define Hc   4
#define NFc  8
#define DHc  64
#define SCALEF 0.125f     // DH^-0.5
#define EPSF   1e-8f
#define LNEPS  1e-5f

// -------- scratch (device globals: allocation-free) --------
__device__ float g_stats[2 * 131072];          // per-row mean,rstd of inputs
__device__ float g_K[33554432];                // [B,N,256]
__device__ float g_V[33554432];                // [B,N,256]
__device__ float g_attn[32 * 32 * 4096];       // [b][ih][j] raw softmax
__device__ float g_rowsum[1024];               // [b][ih]
__device__ float g_fill[65536];                // fillers [b,slot,256]
__device__ float g_f[65536];                   // LN(fillers)
__device__ float g_q[65536];                   // q
__device__ float g_upd[65536];                 // updates
__device__ float g_gates[2 * 256 * 768];       // [gi|gh][row][768]

// ---------------- helpers ----------------
__device__ __forceinline__ unsigned smem_u32(const void* p) {
    return (unsigned)__cvta_generic_to_shared(p);
}
__device__ __forceinline__ void ldm4(unsigned* r, unsigned a) {
    asm volatile("ldmatrix.sync.aligned.m8n8.x4.shared.b16 {%0,%1,%2,%3},[%4];\n"
                 : "=r"(r[0]), "=r"(r[1]), "=r"(r[2]), "=r"(r[3]) : "r"(a));
}
__device__ __forceinline__ void mma_bf16(float* c, const unsigned* a, const unsigned* b) {
    asm volatile(
        "mma.sync.aligned.m16n8k16.row.col.f32.bf16.bf16.f32 "
        "{%0,%1,%2,%3},{%4,%5,%6,%7},{%8,%9},{%0,%1,%2,%3};\n"
        : "+f"(c[0]), "+f"(c[1]), "+f"(c[2]), "+f"(c[3])
        : "r"(a[0]), "r"(a[1]), "r"(a[2]), "r"(a[3]), "r"(b[0]), "r"(b[1]));
}
__device__ __forceinline__ unsigned packh(__nv_bfloat16 a, __nv_bfloat16 b) {
    unsigned short lo = __bfloat16_as_ushort(a);
    unsigned short hi = __bfloat16_as_ushort(b);
    return (unsigned)lo | ((unsigned)hi << 16);
}
__device__ __forceinline__ unsigned pack2(float a, float b) {
    return packh(__float2bfloat16(a), __float2bfloat16(b));
}

// ---------------- row stats of inputs (mean, rstd over FD=256) ----------------
__global__ void k_rowstats(const float* __restrict__ x) {
    int warp = (blockIdx.x * blockDim.x + threadIdx.x) >> 5;   // row id
    int lane = threadIdx.x & 31;
    const float* r = x + (size_t)warp * 256;
    float v[8];
    float s = 0.f;
#pragma unroll
    for (int u = 0; u < 8; u++) { v[u] = r[lane + 32 * u]; s += v[u]; }
#pragma unroll
    for (int o = 16; o > 0; o >>= 1) s += __shfl_xor_sync(0xffffffffu, s, o);
    float m = s * (1.f / 256.f);
    float ss = 0.f;
#pragma unroll
    for (int u = 0; u < 8; u++) { float d = v[u] - m; ss += d * d; }
#pragma unroll
    for (int o = 16; o > 0; o >>= 1) ss += __shfl_xor_sync(0xffffffffu, ss, o);
    if (lane == 0) {
        g_stats[2 * warp + 0] = m;
        g_stats[2 * warp + 1] = rsqrtf(ss * (1.f / 256.f) + LNEPS);
    }
}

// ---------------- big GEMM on tensor cores (bf16 3x-split, fp32 accum) -------
// K = LN(x) @ Wk^T, V = LN(x) @ Wv^T.
// grid (4, 1024): blockIdx.x = {ntile, kv} (fast-varying -> L2 reuse of A rows),
// blockIdx.y = m-tile. Block: 128x128, 8 warps (2x4), warp tile 64x32.
__global__ void __launch_bounds__(256, 2)
k_kv_gemm(const float* __restrict__ x,
          const float* __restrict__ Wk, const float* __restrict__ Wv,
          const float* __restrict__ lg, const float* __restrict__ lb) {
    __shared__ __nv_bfloat16 Ah[128][24], Al[128][24], Bh[128][24], Bl[128][24];
    __shared__ float gs[256], bsm[256];

    int t = threadIdx.x;
    gs[t]  = lg[t];
    bsm[t] = lb[t];

    int ntile = blockIdx.x & 1, kv = blockIdx.x >> 1;
    int row0 = blockIdx.y * 128;
    int col0 = ntile * 128;
    const float* W = kv ? Wv : Wk;
    float* out     = kv ? g_V : g_K;

    int wid = t >> 5, lane = t & 31;
    int wm0 = (wid >> 2) * 64;    // warp row base (0 or 64)
    int wn0 = (wid & 3) * 32;     // warp col base (0,32,64,96)

    // global load mapping: 2 threads per row, 8 floats each
    int lrow  = t >> 1;
    int lhalf = (t & 1) * 8;
    float mean = g_stats[2 * (row0 + lrow) + 0];
    float rstd = g_stats[2 * (row0 + lrow) + 1];
    const float* arow = x + (size_t)(row0 + lrow) * 256;
    const float* brow = W + (size_t)(col0 + lrow) * 256;

    // ldmatrix lane addressing
    int lr = (lane & 7) + ((lane >> 3) & 1) * 8;
    int lk = (lane >> 4) * 8;
    unsigned aAh[4], aAl[4], aBh[2], aBl[2];
#pragma unroll
    for (int mt = 0; mt < 4; mt++) {
        aAh[mt] = smem_u32(&Ah[wm0 + mt * 16 + lr][lk]);
        aAl[mt] = smem_u32(&Al[wm0 + mt * 16 + lr][lk]);
    }
#pragma unroll
    for (int g2 = 0; g2 < 2; g2++) {
        aBh[g2] = smem_u32(&Bh[wn0 + g2 * 16 + lr][lk]);
        aBl[g2] = smem_u32(&Bl[wn0 + g2 * 16 + lr][lk]);
    }

    float acc[4][4][4];
#pragma unroll
    for (int i = 0; i < 4; i++)
#pragma unroll
        for (int j = 0; j < 4; j++)
#pragma unroll
            for (int r = 0; r < 4; r++) acc[i][j][r] = 0.f;

    for (int k0 = 0; k0 < 256; k0 += 16) {
        __syncthreads();
        // ---- A tile: load, LN, split, store
        {
            float4 va = *(const float4*)(arow + k0 + lhalf);
            float4 vb = *(const float4*)(arow + k0 + lhalf + 4);
            float v[8] = {va.x, va.y, va.z, va.w, vb.x, vb.y, vb.z, vb.w};
            unsigned Hh[4], Ll[4];
#pragma unroll
            for (int p = 0; p < 4; p++) {
                float v0 = (v[2*p]   - mean) * rstd * gs[k0 + lhalf + 2*p]     + bsm[k0 + lhalf + 2*p];
                float v1 = (v[2*p+1] - mean) * rstd * gs[k0 + lhalf + 2*p + 1] + bsm[k0 + lhalf + 2*p + 1];
                __nv_bfloat16 h0 = __float2bfloat16(v0);
                __nv_bfloat16 h1 = __float2bfloat16(v1);
                Hh[p] = packh(h0, h1);
                Ll[p] = pack2(v0 - __bfloat162float(h0), v1 - __bfloat162float(h1));
            }
            *(uint4*)&Ah[lrow][lhalf] = make_uint4(Hh[0], Hh[1], Hh[2], Hh[3]);
            *(uint4*)&Al[lrow][lhalf] = make_uint4(Ll[0], Ll[1], Ll[2], Ll[3]);
        }
        // ---- B tile: load, split, store
        {
            float4 va = *(const float4*)(brow + k0 + lhalf);
            float4 vb = *(const float4*)(brow + k0 + lhalf + 4);
            float v[8] = {va.x, va.y, va.z, va.w, vb.x, vb.y, vb.z, vb.w};
            unsigned Hh[4], Ll[4];
#pragma unroll
            for (int p = 0; p < 4; p++) {
                __nv_bfloat16 h0 = __float2bfloat16(v[2*p]);
                __nv_bfloat16 h1 = __float2bfloat16(v[2*p+1]);
                Hh[p] = packh(h0, h1);
                Ll[p] = pack2(v[2*p] - __bfloat162float(h0), v[2*p+1] - __bfloat162float(h1));
            }
            *(uint4*)&Bh[lrow][lhalf] = make_uint4(Hh[0], Hh[1], Hh[2], Hh[3]);
            *(uint4*)&Bl[lrow][lhalf] = make_uint4(Ll[0], Ll[1], Ll[2], Ll[3]);
        }
        __syncthreads();

        unsigned afh[4][4], afl[4][4], bfh[2][4], bfl[2][4];
#pragma unroll
        for (int mt = 0; mt < 4; mt++) { ldm4(afh[mt], aAh[mt]); ldm4(afl[mt], aAl[mt]); }
#pragma unroll
        for (int g2 = 0; g2 < 2; g2++) { ldm4(bfh[g2], aBh[g2]); ldm4(bfl[g2], aBl[g2]); }

#pragma unroll
        for (int mt = 0; mt < 4; mt++)
#pragma unroll
            for (int nt = 0; nt < 4; nt++) {
                int g2 = nt >> 1, hf = nt & 1;
                unsigned bh[2] = {bfh[g2][hf], bfh[g2][hf + 2]};
                unsigned bl[2] = {bfl[g2][hf], bfl[g2][hf + 2]};
                mma_bf16(acc[mt][nt], afh[mt], bh);
                mma_bf16(acc[mt][nt], afh[mt], bl);
                mma_bf16(acc[mt][nt], afl[mt], bh);
            }
    }

    int cr = lane >> 2, cc = 2 * (lane & 3);
#pragma unroll
    for (int mt = 0; mt < 4; mt++)
#pragma unroll
        for (int nt = 0; nt < 4; nt++) {
            int r = row0 + wm0 + mt * 16 + cr;
            int c = col0 + wn0 + nt * 8 + cc;
            float2 v0 = {acc[mt][nt][0], acc[mt][nt][1]};
            float2 v1 = {acc[mt][nt][2], acc[mt][nt][3]};
            *(float2*)&out[(size_t)r * 256 + c]       = v0;
            *(float2*)&out[(size_t)(r + 8) * 256 + c] = v1;
        }
}

// ---------------- small GEMM: C[256 x Ncols] = A[256,256] @ W[Ncols,256]^T + bias
// mode 0: A=g_f   -> C=g_q            (ldc 256, no bias)
// mode 1: A=g_upd -> C=g_gates        (ldc 768, bias b_ih)
// mode 2: A=g_fill-> C=g_gates+196608 (ldc 768, bias b_hh)
__global__ void __launch_bounds__(256)
k_gemm64(int mode, const float* __restrict__ W, const float* __restrict__ bias) {
    const float* A;
    float* C;
    int ldc;
    if (mode == 0)      { A = g_f;    C = g_q;              ldc = 256; }
    else if (mode == 1) { A = g_upd;  C = g_gates;          ldc = 768; }
    else                { A = g_fill; C = g_gates + 196608; ldc = 768; }

    __shared__ float As[64][17];
    __shared__ float Bs[64][17];
    int t = threadIdx.x;
    int row0 = blockIdx.x * 64, col0 = blockIdx.y * 64;
    int tx = t & 15, ty = t >> 4;

    float acc[4][4];
#pragma unroll
    for (int i = 0; i < 4; i++)
#pragma unroll
        for (int j = 0; j < 4; j++) acc[i][j] = 0.f;

    for (int k0 = 0; k0 < 256; k0 += 16) {
        __syncthreads();
        {
            int row = t >> 2, kp = t & 3;
            float4 a4 = *(const float4*)(A + (size_t)(row0 + row) * 256 + k0 + kp * 4);
            As[row][kp * 4 + 0] = a4.x;
            As[row][kp * 4 + 1] = a4.y;
            As[row][kp * 4 + 2] = a4.z;
            As[row][kp * 4 + 3] = a4.w;
            float4 b4 = *(const float4*)(W + (size_t)(col0 + row) * 256 + k0 + kp * 4);
            Bs[row][kp * 4 + 0] = b4.x;
            Bs[row][kp * 4 + 1] = b4.y;
            Bs[row][kp * 4 + 2] = b4.z;
            Bs[row][kp * 4 + 3] = b4.w;
        }
        __syncthreads();
#pragma unroll
        for (int kk = 0; kk < 16; kk++) {
            float a[4], bb[4];
#pragma unroll
            for (int i = 0; i < 4; i++) a[i]  = As[ty + 16 * i][kk];
#pragma unroll
            for (int j = 0; j < 4; j++) bb[j] = Bs[tx + 16 * j][kk];
#pragma unroll
            for (int i = 0; i < 4; i++)
#pragma unroll
                for (int j = 0; j < 4; j++) acc[i][j] += a[i] * bb[j];
        }
    }
#pragma unroll
    for (int i = 0; i < 4; i++)
#pragma unroll
        for (int j = 0; j < 4; j++) {
            float c = acc[i][j];
            if (bias) c += bias[col0 + tx + 16 * j];
            C[(size_t)(row0 + ty + 16 * i) * ldc + col0 + tx + 16 * j] = c;
        }
}

// ---------------- LN(fillers) + zero rowsum + zero g_upd ----------------
__global__ void k_lnfill(const float* __restrict__ g, const float* __restrict__ b) {
    int t = threadIdx.x;
    int gt = blockIdx.x * 256 + t;         // 8192 threads total
#pragma unroll
    for (int u = 0; u < 8; u++) g_upd[gt + 8192 * u] = 0.f;
    if (gt < 1024) g_rowsum[gt] = 0.f;

    int row  = blockIdx.x * 8 + (t >> 5);  // 256 rows total
    int lane = t & 31;
    const float* r = g_fill + row * 256;
    float v[8];
    float s = 0.f;
#pragma unroll
    for (int u = 0; u < 8; u++) { v[u] = r[lane + 32 * u]; s += v[u]; }
#pragma unroll
    for (int o = 16; o > 0; o >>= 1) s += __shfl_xor_sync(0xffffffffu, s, o);
    float m = s * (1.f / 256.f);
    float ss = 0.f;
#pragma unroll
    for (int u = 0; u < 8; u++) { float d = v[u] - m; ss += d * d; }
#pragma unroll
    for (int o = 16; o > 0; o >>= 1) ss += __shfl_xor_sync(0xffffffffu, ss, o);
    float rstd = rsqrtf(ss * (1.f / 256.f) + LNEPS);
#pragma unroll
    for (int u = 0; u < 8; u++) {
        int c = lane + 32 * u;
        g_f[row * 256 + c] = (v[u] - m) * rstd * g[c] + b[c];
    }
}

// ---------------- dots + inverted softmax (over 32 (slot,head) per (b,j)) ----------------
__global__ void __launch_bounds__(256)
k_dots(int last, float* __restrict__ attn_out) {
    int b = blockIdx.x;
    int w = threadIdx.x >> 5, lane = threadIdx.x & 31;
    int j0 = blockIdx.y * 256 + w * 32;

    __shared__ float buf[8][32][33];

    int i = lane >> 2, h = lane & 3;
    const float4* q4 = (const float4*)(g_q + b * 2048 + i * 256 + h * 64);
    float4 qr[16];
#pragma unroll
    for (int p = 0; p < 16; p++) {
        float4 q = q4[p];
        q.x *= SCALEF; q.y *= SCALEF; q.z *= SCALEF; q.w *= SCALEF;
        qr[p] = q;
    }

    float rs = 0.f;
    for (int jj = 0; jj < 32; jj++) {
        int j = j0 + jj;
        const float4* k4 = (const float4*)(g_K + (size_t)(b * 4096 + j) * 256 + h * 64);
        float dot = 0.f;
#pragma unroll
        for (int p = 0; p < 16; p++) {
            float4 kv = k4[p];
            dot += qr[p].x * kv.x + qr[p].y * kv.y + qr[p].z * kv.z + qr[p].w * kv.w;
        }
        float mx = dot;
#pragma unroll
        for (int o = 16; o > 0; o >>= 1) mx = fmaxf(mx, __shfl_xor_sync(0xffffffffu, mx, o));
        float e = expf(dot - mx);
        float sm = e;
#pragma unroll
        for (int o = 16; o > 0; o >>= 1) sm += __shfl_xor_sync(0xffffffffu, sm, o);
        float at = e / sm;
        buf[w][lane][jj] = at;
        rs += at;
    }
    atomicAdd(&g_rowsum[b * 32 + lane], rs);
    __syncwarp();

#pragma unroll 4
    for (int r = 0; r < 32; r++)
        g_attn[((size_t)b * 32 + r) * 4096 + j0 + lane] = buf[w][r][lane];

    if (last) {
#pragma unroll
        for (int ii = 0; ii < 8; ii++) {
            float v = 0.25f * (buf[w][4 * ii + 0][lane] + buf[w][4 * ii + 1][lane] +
                               buf[w][4 * ii + 2][lane] + buf[w][4 * ii + 3][lane]);
            attn_out[((size_t)b * 8 + ii) * 4096 + j0 + lane] = v;
        }
    }
}

// ---------------- updates = einsum('bjhd,bihj->bihd', V, a) ----------------
__global__ void __launch_bounds__(256)
k_updates() {
    int b = blockIdx.x, h = blockIdx.y, jc = blockIdx.z;
    int t = threadIdx.x;
    int d = t & 63, ig = t >> 6;
    int i0 = 2 * ig, i1 = i0 + 1;

    __shared__ float a_s[8][64];
    __shared__ float inv_s[8];
    if (t < 8) inv_s[t] = 1.f / (g_rowsum[b * 32 + t * 4 + h] + 4096.f * EPSF);

    float acc0 = 0.f, acc1 = 0.f;
    int jbase = jc * 512;
    for (int jt = 0; jt < 512; jt += 64) {
        __syncthreads();
#pragma unroll
        for (int s = 0; s < 2; s++) {
            int e = t + 256 * s;
            int ri = e >> 6, jj = e & 63;
            a_s[ri][jj] = (g_attn[((size_t)b * 32 + ri * 4 + h) * 4096 + jbase + jt + jj] + EPSF) * inv_s[ri];
        }
        __syncthreads();
        const float* vp = g_V + (size_t)(b * 4096 + jbase + jt) * 256 + h * 64 + d;
#pragma unroll 4
        for (int jj = 0; jj < 64; jj++) {
            float vv = vp[jj * 256];
            acc0 += vv * a_s[i0][jj];
            acc1 += vv * a_s[i1][jj];
        }
    }
    atomicAdd(&g_upd[b * 2048 + i0 * 256 + h * 64 + d], acc0);
    atomicAdd(&g_upd[b * 2048 + i1 * 256 + h * 64 + d], acc1);
}

// ---------------- GRU elementwise ----------------
__global__ void k_gru() {
    int idx = blockIdx.x * blockDim.x + threadIdx.x;   // 65536
    int r = idx >> 8, c = idx & 255;
    const float* gi = g_gates + (size_t)r * 768;
    const float* gh = g_gates + 196608 + (size_t)r * 768;
    float ir = gi[c], iz = gi[c + 256], in = gi[c + 512];
    float hr = gh[c], hz = gh[c + 256], hn = gh[c + 512];
    float rr = 1.f / (1.f + expf(-(ir + hr)));
    float zz = 1.f / (1.f + expf(-(iz + hz)));
    float nn = tanhf(in + rr * hn);
    float hp = g_fill[idx];
    g_fill[idx] = (1.f - zz) * nn + zz * hp;
}

// ---------------- copies ----------------
__global__ void k_copyin(const float* __restrict__ src) {
    int idx = blockIdx.x * blockDim.x + threadIdx.x;
    g_fill[idx] = src[idx];
}
__global__ void k_copyout(float* __restrict__ dst) {
    int idx = blockIdx.x * blockDim.x + threadIdx.x;
    dst[idx] = g_fill[idx];
}

// ---------------- launcher ----------------
extern "C" void kernel_launch(void* const* d_in, const int* in_sizes, int n_in,
                              void* d_out, int out_size) {
    const float* inputs = (const float*)d_in[0];
    const float* cond   = (const float*)d_in[1];
    const float* Wq     = (const float*)d_in[2];
    const float* Wk     = (const float*)d_in[3];
    const float* Wv     = (const float*)d_in[4];
    const float* W_ih   = (const float*)d_in[5];
    const float* W_hh   = (const float*)d_in[6];
    const float* b_ih   = (const float*)d_in[7];
    const float* b_hh   = (const float*)d_in[8];
    const float* lig    = (const float*)d_in[9];
    const float* lib    = (const float*)d_in[10];
    const float* lfg    = (const float*)d_in[11];
    const float* lfb    = (const float*)d_in[12];
    float* out = (float*)d_out;

    k_rowstats<<<16384, 256>>>(inputs);
    k_kv_gemm<<<dim3(4, 1024), 256>>>(inputs, Wk, Wv, lig, lib);
    k_copyin<<<64, 1024>>>(cond);

    for (int it = 0; it < 3; it++) {
        k_lnfill<<<32, 256>>>(lfg, lfb);
        k_gemm64<<<dim3(4, 4), 256>>>(0, Wq, (const float*)0);
        k_dots<<<dim3(32, 16), 256>>>(it == 2 ? 1 : 0, out + 65536);
        k_updates<<<dim3(32, 4, 8), 256>>>();
        k_gemm64<<<dim3(4, 12), 256>>>(1, W_ih, b_ih);
        k_gemm64<<<dim3(4, 12), 256>>>(2, W_hh, b_hh);
        k_gru<<<256, 256>>>();
    }
    k_copyout<<<64, 1024>>>(out);
}